// round 12
// baseline (speedup 1.0000x reference)
#include <cuda_runtime.h>
#include <cstdint>

// Circuit in linear probability space (one log at the end):
//   p_v = exp(l_v);  s = p1(1-p2) + (1-p1)p2;  t = p1*p2
//   out = log(p0*s + (1-p0)*t)
// Identical to the reference's nested logsumexp (slot-9's -1000 disjunct
// exp-underflows to exactly 0 there too).
__device__ __forceinline__ float circuit_eval(float l0, float l1, float l2) {
    float p0 = __expf(l0);
    float p1 = __expf(l1);
    float p2 = __expf(l2);

    float t  = p1 * p2;
    float a  = __fmaf_rn(-p1, p2, p1);    // p1*(1-p2)
    float b  = __fmaf_rn(-p1, p2, p2);    // (1-p1)*p2
    float s  = a + b;

    float q0 = 1.0f - p0;
    float x  = __fmaf_rn(p0, s, q0 * t);
    return __logf(x);
}

// R11 shape with the fill path swapped to TMA bulk copies:
//   tile = 512 elements (6144B in), 4-stage smem ring, one UBLKCP per stage
//   completing on an mbarrier (expect_tx). Load side uses zero LSU/L1tex
//   wavefronts and one issue slot per tile. Stores remain direct STG.128.
static constexpr int THREADS        = 128;
static constexpr int ELEMS_PER_TILE = 512;
static constexpr int F4_PER_TILE    = 384;            // 512 * 3 / 4
static constexpr int TILE_IN_BYTES  = F4_PER_TILE * 16;  // 6144
static constexpr int STAGES         = 4;

__global__ void __launch_bounds__(THREADS)
circuit_kernel(const float4* __restrict__ in, float4* __restrict__ out,
               int n_tiles) {
    __shared__ __align__(128) float4 buf[STAGES][F4_PER_TILE];
    __shared__ __align__(8) unsigned long long mbar[STAGES];

    const int t      = threadIdx.x;
    const int stride = gridDim.x;

    const uint32_t mbar_base = (uint32_t)__cvta_generic_to_shared(&mbar[0]);

    if (t == 0) {
#pragma unroll
        for (int s = 0; s < STAGES; s++) {
            asm volatile("mbarrier.init.shared.b64 [%0], 1;"
                         :: "r"(mbar_base + s * 8) : "memory");
        }
        // Order mbarrier init before async-proxy (TMA) use.
        asm volatile("fence.proxy.async.shared::cta;" ::: "memory");
    }
    __syncthreads();

    // One bulk copy per tile: 6144B global -> smem stage, completes on mbar[s].
    auto issue = [&](int tile, int s) {
        if (tile < n_tiles) {
            uint32_t mb  = mbar_base + s * 8;
            uint32_t dst = (uint32_t)__cvta_generic_to_shared(&buf[s][0]);
            const float4* src = in + (size_t)tile * F4_PER_TILE;
            asm volatile("mbarrier.arrive.expect_tx.shared.b64 _, [%0], %1;"
                         :: "r"(mb), "r"(TILE_IN_BYTES) : "memory");
            asm volatile(
                "cp.async.bulk.shared::cluster.global.mbarrier::complete_tx::bytes"
                " [%0], [%1], %2, [%3];"
                :: "r"(dst), "l"(src), "r"(TILE_IN_BYTES), "r"(mb) : "memory");
        }
    };

    // Prologue: fill the ring.
    if (t == 0) {
#pragma unroll
        for (int s = 0; s < STAGES; s++)
            issue(blockIdx.x + s * stride, s);
    }

    int stage = 0, phase = 0;
    int ahead = blockIdx.x + STAGES * stride;
    for (int i = blockIdx.x; i < n_tiles; i += stride) {
        // Wait for tile i's bulk copy (acquire orders TMA writes before LDS).
        {
            uint32_t mb = mbar_base + stage * 8;
            unsigned done;
            do {
                asm volatile(
                    "{\n\t.reg .pred p;\n\t"
                    "mbarrier.try_wait.parity.acquire.cta.shared::cta.b64 p, [%1], %2, 0x989680;\n\t"
                    "selp.b32 %0, 1, 0, p;\n\t}"
                    : "=r"(done) : "r"(mb), "r"(phase) : "memory");
            } while (!done);
        }

        // Thread t owns elements 4t..4t+3 = float4s 3t..3t+2 of the tile.
        // 48B lane stride -> banks {12l..12l+3 mod 32}: conflict-free LDS.128.
        float4 a = buf[stage][3 * t + 0];
        float4 b = buf[stage][3 * t + 1];
        float4 c = buf[stage][3 * t + 2];

        float4 r;
        r.x = circuit_eval(a.x, a.y, a.z);
        r.y = circuit_eval(a.w, b.x, b.y);
        r.z = circuit_eval(b.z, b.w, c.x);
        r.w = circuit_eval(c.y, c.z, c.w);

        // Coalesced store (contiguous 512B per warp).
        out[(size_t)i * (ELEMS_PER_TILE / 4) + t] = r;

        // All threads done reading this stage before tid0 refills it.
        __syncthreads();
        if (t == 0) issue(ahead, stage);
        ahead += stride;
        if (++stage == STAGES) { stage = 0; phase ^= 1; }
    }
}

// Tail for elements beyond the last full CTA tile (not hit for B=4194304).
__global__ void circuit_tail_kernel(const float* __restrict__ in,
                                    float* __restrict__ out,
                                    int start, int n) {
    int i = start + blockIdx.x * blockDim.x + threadIdx.x;
    if (i >= n) return;
    out[i] = circuit_eval(in[3 * i + 0], in[3 * i + 1], in[3 * i + 2]);
}

extern "C" void kernel_launch(void* const* d_in, const int* in_sizes, int n_in,
                              void* d_out, int out_size) {
    const float* log_probs = (const float*)d_in[0];
    float* out = (float*)d_out;

    int B = out_size;                    // output is (1, B) floats
    int n_tiles = B / ELEMS_PER_TILE;    // 512 elements per CTA tile

    if (n_tiles > 0) {
        // One exact wave: 148 SMs x 8 CTAs (24.6KB smem, 128 thr each).
        int blocks = 8 * 148;
        if (blocks > n_tiles) blocks = n_tiles;
        circuit_kernel<<<blocks, THREADS>>>(
            (const float4*)log_probs, (float4*)out, n_tiles);
    }
    int done = n_tiles * ELEMS_PER_TILE;
    if (done < B) {
        int rem = B - done;
        circuit_tail_kernel<<<(rem + 255) / 256, 256>>>(log_probs, out, done, B);
    }
}